// round 12
// baseline (speedup 1.0000x reference)
#include <cuda_runtime.h>
#include <math.h>
#include <stdint.h>

// CRF loss: L=512 seq, B=512 batch, T=128 tags.
#define LL 512
#define BB 512
#define TT 128
#define NBC 2             // batches per CTA (two pipelined streams)
#define NCTA (BB/NBC)     // 256 CTAs -> 2 CTAs/SM
#define NTHREADS 256
#define PQ 36             // padded j-quarter stride (floats)
#define PB (4*PQ)         // padded per-batch alpha row
#define LN2F 0.6931471805599453f

__device__ float g_logZ[BB];
__device__ float g_num[BB];

union F4U { float4 v; struct { unsigned long long p01, p23; } u; };

__device__ __forceinline__ unsigned long long ffma2(unsigned long long a,
                                                    unsigned long long b,
                                                    unsigned long long c) {
    unsigned long long d;
    asm("fma.rn.f32x2 %0, %1, %2, %3;" : "=l"(d) : "l"(a), "l"(b), "l"(c));
    return d;
}
__device__ __forceinline__ unsigned long long packf2(float lo, float hi) {
    unsigned long long r;
    asm("mov.b64 %0, {%1,%2};" : "=l"(r) : "f"(lo), "f"(hi));
    return r;
}
__device__ __forceinline__ float2 unpackf2(unsigned long long v) {
    float2 f;
    asm("mov.b64 {%0,%1}, %2;" : "=f"(f.x), "=f"(f.y) : "l"(v));
    return f;
}

// Org: 8 warps, 2 batch streams half-step staggered. Lane: jq = lane>>3
// (j-quarter), kidx = lane&7, k0 = w*16+kidx*2. FMA tile per stream:
// 32j x 2k = 32 FFMA2. E: 32 u64 regs shared by both streams.
// Each barrier interval: FMA(stream X) overlaps tail(stream Y).
__global__ __launch_bounds__(NTHREADS, 2)
void crf_forward(const float* __restrict__ emissions,
                 const int* __restrict__ mask,
                 const float* __restrict__ start_t,
                 const float* __restrict__ end_t,
                 const float* __restrict__ trans)
{
    __shared__ __align__(16) float sP0A[PB], sP0B[PB];   // batch-0 ping/pong
    __shared__ __align__(16) float sP1A[PB], sP1B[PB];   // batch-1 ping/pong
    __shared__ __align__(16) float sZf[NBC][TT];
    __shared__ int sEa[NBC];

    const int tid  = threadIdx.x;
    const int w    = tid >> 5;
    const int lane = tid & 31;
    const int jq   = lane >> 3;          // j-quarter
    const int kidx = lane & 7;
    const int k0   = w * 16 + kidx * 2;  // this lane's 2 output tags
    const int gb0  = blockIdx.x * NBC;
    const int gb1  = gb0 + 1;
    const int ka2  = (k0 >> 5) * PQ + (k0 & 31);   // padded addr of k0 (float2)
    const int jb   = jq * PQ;                       // lane's j-quarter offset

    // ---- E: 32 j x 2 k per lane, register-resident ----
    unsigned long long eR[8][2][2];
    #pragma unroll
    for (int t = 0; t < 8; ++t) {
        #pragma unroll
        for (int sub = 0; sub < 2; ++sub) {
            int j = jq * 32 + t * 4 + sub * 2;
            eR[t][sub][0] = packf2(__expf(trans[j * TT + k0]),
                                   __expf(trans[(j + 1) * TT + k0]));
            eR[t][sub][1] = packf2(__expf(trans[j * TT + k0 + 1]),
                                   __expf(trans[(j + 1) * TT + k0 + 1]));
        }
    }

    // ---- init p~0 into A buffers (jq==0 lanes cover all 128 k) ----
    if (jq == 0) {
        const float2 st = *(const float2*)(start_t + k0);
        const float2 e0 = *(const float2*)(emissions + (size_t)gb0 * TT + k0);
        const float2 e1 = *(const float2*)(emissions + (size_t)gb1 * TT + k0);
        *(float2*)&sP0A[ka2] = make_float2(__expf(st.x + e0.x), __expf(st.y + e0.y));
        *(float2*)&sP1A[ka2] = make_float2(__expf(st.x + e1.x), __expf(st.y + e1.y));
    }
    __syncthreads();

    int e0acc = 0, e1acc = 0;

    // per-stream prefetched emission pair + mask (for step 1)
    float2 em0 = *(const float2*)(emissions + ((size_t)1 * BB + gb0) * TT + k0);
    float2 em1 = *(const float2*)(emissions + ((size_t)1 * BB + gb1) * TT + k0);
    int mk0 = mask[1 * BB + gb0];
    int mk1 = mask[1 * BB + gb1];

    // ---- FMA for one stream: 32 FFMA2 into two u64 chains ----
    #define FMABODY(Pin, A0, A1)                                            \
    {                                                                        \
        A0 = 0ull; A1 = 0ull;                                                \
        _Pragma("unroll")                                                    \
        for (int t = 0; t < 8; ++t) {                                        \
            F4U pv; pv.v = *(const float4*)((Pin) + jb + 4 * t);             \
            A0 = ffma2(pv.u.p01, eR[t][0][0], A0);                           \
            A1 = ffma2(pv.u.p01, eR[t][0][1], A1);                           \
            A0 = ffma2(pv.u.p23, eR[t][1][0], A0);                           \
            A1 = ffma2(pv.u.p23, eR[t][1][1], A1);                           \
        }                                                                    \
    }

    // ---- tail for one stream (step I): reduce, renorm, write p_I ----
    #define TAILBODY(Pin, Pout, A0, A1, EM, MK, EACC, I, GBX)               \
    {                                                                        \
        const float4 ev = *(const float4*)&(Pin)[0];                         \
        float s  = (ev.x + ev.y) + (ev.z + ev.w);                            \
        int   es = ((__float_as_int(s) >> 23) & 255) - 126;                  \
        float scale = __int_as_float((127 - es) << 23);                      \
        float fx = __expf(EM.x) * scale;                                     \
        float fy = __expf(EM.y) * scale;                                     \
        float2 oldp = *(const float2*)&(Pin)[ka2];                           \
        int inx = ((I) + 1 < LL) ? (I) + 1 : LL - 1;                         \
        float2 nem = *(const float2*)(emissions + ((size_t)inx * BB + (GBX)) * TT + k0); \
        int   nmk = mask[inx * BB + (GBX)];                                  \
        float2 h0 = unpackf2(A0), h1 = unpackf2(A1);                         \
        float q0 = h0.x + h0.y;                                              \
        float q1 = h1.x + h1.y;                                              \
        q0 += __shfl_xor_sync(0xffffffffu, q0, 8);                           \
        q1 += __shfl_xor_sync(0xffffffffu, q1, 8);                           \
        q0 += __shfl_xor_sync(0xffffffffu, q0, 16);                          \
        q1 += __shfl_xor_sync(0xffffffffu, q1, 16);                          \
        if (MK) EACC += es;                                                  \
        if (jq == 0) {                                                       \
            float2 o;                                                        \
            if (MK) { o.x = q0 * fx; o.y = q1 * fy; }                        \
            else    { o = oldp; }                                            \
            *(float2*)&(Pout)[ka2] = o;                                      \
        }                                                                    \
        EM = nem; MK = nmk;                                                  \
    }

    // One full step for both streams (two barrier intervals).
    // Entry invariant: a00/a01 hold stream-0's acc for step I (computed last interval).
    #define ITER(I, P0in, P0out, P1in, P1out)                               \
    {                                                                        \
        unsigned long long b10, b11;                                         \
        FMABODY(P1in, b10, b11);            /* stream1 FMA step I   */       \
        TAILBODY(P0in, P0out, a00, a01, em0, mk0, e0acc, I, gb0);            \
        __syncthreads();                                                     \
        FMABODY(P0out, a00, a01);           /* stream0 FMA step I+1 */       \
        TAILBODY(P1in, P1out, b10, b11, em1, mk1, e1acc, I, gb1);            \
        __syncthreads();                                                     \
    }

    unsigned long long a00, a01;
    FMABODY(sP0A, a00, a01);      // warm-up: stream0 FMA for step 1

    for (int i = 1; i <= 509; i += 2) {
        ITER(i,     sP0A, sP0B, sP1A, sP1B);
        ITER(i + 1, sP0B, sP0A, sP1B, sP1A);
    }
    ITER(511, sP0A, sP0B, sP1A, sP1B);
    #undef ITER
    #undef TAILBODY
    #undef FMABODY

    // ---- finalize: p_511 in B buffers ----
    if (jq == 0) {
        const float2 en = *(const float2*)(end_t + k0);
        float2 p0 = *(const float2*)&sP0B[ka2];
        float2 p1 = *(const float2*)&sP1B[ka2];
        *(float2*)&sZf[0][k0] = make_float2(p0.x * __expf(en.x), p0.y * __expf(en.y));
        *(float2*)&sZf[1][k0] = make_float2(p1.x * __expf(en.x), p1.y * __expf(en.y));
    }
    if (tid == 0) { sEa[0] = e0acc; sEa[1] = e1acc; }
    __syncthreads();
    if (w == 0) {
        #pragma unroll
        for (int b = 0; b < NBC; ++b) {
            float v = sZf[b][lane] + sZf[b][lane + 32]
                    + sZf[b][lane + 64] + sZf[b][lane + 96];
            v += __shfl_xor_sync(0xffffffffu, v, 1);
            v += __shfl_xor_sync(0xffffffffu, v, 2);
            v += __shfl_xor_sync(0xffffffffu, v, 4);
            v += __shfl_xor_sync(0xffffffffu, v, 8);
            v += __shfl_xor_sync(0xffffffffu, v, 16);
            if (lane == 0)
                g_logZ[blockIdx.x * NBC + b] = (float)sEa[b] * LN2F + logf(v);
        }
    }
}

// Numerator: one block per batch.
__global__ void crf_num(const float* __restrict__ emissions,
                        const int*   __restrict__ tags,
                        const int*   __restrict__ mask,
                        const float* __restrict__ start_t,
                        const float* __restrict__ end_t,
                        const float* __restrict__ trans)
{
    const int b   = blockIdx.x;
    const int tid = threadIdx.x;
    __shared__ float rf[256];
    __shared__ int   ri[256];

    float loc = 0.f;
    int   cnt = 0;
    for (int i = tid; i < LL; i += 256) {
        int tag = tags[i * BB + b];
        int m   = mask[i * BB + b];
        if (m) {
            loc += emissions[((size_t)i * BB + b) * TT + tag];
            cnt++;
            if (i > 0) loc += trans[tags[(i - 1) * BB + b] * TT + tag];
        }
        if (i == 0) loc += start_t[tag];
    }
    rf[tid] = loc; ri[tid] = cnt;
    __syncthreads();
    #pragma unroll
    for (int s = 128; s > 0; s >>= 1) {
        if (tid < s) { rf[tid] += rf[tid + s]; ri[tid] += ri[tid + s]; }
        __syncthreads();
    }
    if (tid == 0) {
        int ends = ri[0] - 1;
        if (ends < 0) ends = 0;
        g_num[b] = rf[0] + end_t[tags[ends * BB + b]];
    }
}

__global__ void crf_final(float* __restrict__ out)
{
    __shared__ float r[512];
    const int tid = threadIdx.x;
    r[tid] = g_logZ[tid] - g_num[tid];
    __syncthreads();
    #pragma unroll
    for (int s = 256; s > 0; s >>= 1) {
        if (tid < s) r[tid] += r[tid + s];
        __syncthreads();
    }
    if (tid == 0) out[0] = r[0] * (1.0f / (float)BB);
}

extern "C" void kernel_launch(void* const* d_in, const int* in_sizes, int n_in,
                              void* d_out, int out_size)
{
    const float* emissions = (const float*)d_in[0];
    const int*   tags      = (const int*)d_in[1];
    const int*   mask      = (const int*)d_in[2];
    const float* start_t   = (const float*)d_in[3];
    const float* end_t     = (const float*)d_in[4];
    const float* trans     = (const float*)d_in[5];
    float*       out       = (float*)d_out;

    crf_forward<<<NCTA, NTHREADS>>>(emissions, mask, start_t, end_t, trans);
    crf_num<<<BB, 256>>>(emissions, tags, mask, start_t, end_t, trans);
    crf_final<<<1, BB>>>(out);
}

// round 13
// speedup vs baseline: 1.0949x; 1.0949x over previous
#include <cuda_runtime.h>
#include <math.h>
#include <stdint.h>

// CRF loss: L=512 seq, B=512 batch, T=128 tags.
#define LL 512
#define BB 512
#define TT 128
#define NBC 2             // batches per CTA
#define NCTA (BB/NBC)     // 256 CTAs -> 2 CTAs/SM
#define NTHREADS 256
#define PQ 36             // padded j-quarter stride (floats)
#define PB (4*PQ)         // padded per-batch alpha row = 144 floats
#define LN2F 0.6931471805599453f

__device__ float g_logZ[BB];
__device__ float g_num[BB];

union F4U { float4 v; struct { unsigned long long p01, p23; } u; };

__device__ __forceinline__ unsigned long long ffma2(unsigned long long a,
                                                    unsigned long long b,
                                                    unsigned long long c) {
    unsigned long long d;
    asm("fma.rn.f32x2 %0, %1, %2, %3;" : "=l"(d) : "l"(a), "l"(b), "l"(c));
    return d;
}
__device__ __forceinline__ unsigned long long packf2(float lo, float hi) {
    unsigned long long r;
    asm("mov.b64 %0, {%1,%2};" : "=l"(r) : "f"(lo), "f"(hi));
    return r;
}
__device__ __forceinline__ float2 unpackf2(unsigned long long v) {
    float2 f;
    asm("mov.b64 {%0,%1}, %2;" : "=f"(f.x), "=f"(f.y) : "l"(v));
    return f;
}

// Org (R8 family): 8 warps, 2 batches/CTA, 2 CTAs/SM. Lane: jq = lane>>3
// (j-quarter), kidx = lane&7, k0 = w*16+kidx*2. Tile: 32j x 2k x 2b = 64 FFMA2.
// E: 32 u64 regs. Epilogue: lane finalizes ONE element (ab=jq&1, myk=k0+(jq>>1))
// via 3 value-steered shfls; pass-through value kept in register (myp).
__global__ __launch_bounds__(NTHREADS, 2)
void crf_forward(const float* __restrict__ emissions,
                 const int* __restrict__ mask,
                 const float* __restrict__ start_t,
                 const float* __restrict__ end_t,
                 const float* __restrict__ trans)
{
    __shared__ __align__(16) float sPA[NBC * PB];   // ping
    __shared__ __align__(16) float sPB[NBC * PB];   // pong
    __shared__ __align__(16) float sZf[NBC][TT];
    __shared__ int sEa[NBC];

    const int tid  = threadIdx.x;
    const int w    = tid >> 5;
    const int lane = tid & 31;
    const int jq   = lane >> 3;
    const int kidx = lane & 7;
    const int k0   = w * 16 + kidx * 2;
    const int ab   = jq & 1;             // assigned local batch
    const int ak   = jq >> 1;            // assigned k within pair
    const int myk  = k0 + ak;
    const int gba  = blockIdx.x * NBC + ab;
    const int ka   = ab * PB + (myk >> 5) * PQ + (myk & 31);  // addr of my element
    const int jb   = jq * PQ;            // lane's j-quarter offset within a row

    // ---- E: 32 j x 2 k per lane, register-resident ----
    unsigned long long eR[8][2][2];
    #pragma unroll
    for (int t = 0; t < 8; ++t) {
        #pragma unroll
        for (int sub = 0; sub < 2; ++sub) {
            int j = jq * 32 + t * 4 + sub * 2;
            eR[t][sub][0] = packf2(__expf(trans[j * TT + k0]),
                                   __expf(trans[(j + 1) * TT + k0]));
            eR[t][sub][1] = packf2(__expf(trans[j * TT + k0 + 1]),
                                   __expf(trans[(j + 1) * TT + k0 + 1]));
        }
    }

    // ---- init: p~0[ab][myk], kept in myp ----
    float myp = __expf(start_t[myk] + emissions[(size_t)gba * TT + myk]);
    sPA[ka] = myp;
    __syncthreads();

    int e_acc = 0;

    // streaming pointers (step 1) + one-step-ahead prefetch registers
    const float* ep = emissions + ((size_t)BB + gba) * TT + myk;
    const int*   mp = mask + BB + gba;
    float em = *ep;
    int   m  = *mp;
    const size_t ESTRIDE = (size_t)BB * TT;

    // ---- one step: Pin -> Pout (PF: prefetch next step's em/mask) ----
    #define STEP(Pin, Pout, PF)                                                 \
    {                                                                            \
        const float4 ev = *(const float4*)&(Pin)[ab * PB];                       \
        float s  = (ev.x + ev.y) + (ev.z + ev.w);                                \
        int   es = ((__float_as_int(s) >> 23) & 255) - 126;                      \
        float factor = __expf(em) * __int_as_float((127 - es) << 23);            \
        float nem = 0.f; int nm = 0;                                             \
        if (PF) { ep += ESTRIDE; mp += BB; nem = *ep; nm = *mp; }                \
        unsigned long long a00 = 0, a01 = 0, a10 = 0, a11 = 0;                   \
        _Pragma("unroll")                                                        \
        for (int t = 0; t < 8; ++t) {                                            \
            F4U p0; p0.v = *(const float4*)((Pin) + jb + 4 * t);                 \
            F4U p1; p1.v = *(const float4*)((Pin) + PB + jb + 4 * t);            \
            a00 = ffma2(p0.u.p01, eR[t][0][0], a00);                             \
            a01 = ffma2(p0.u.p01, eR[t][0][1], a01);                             \
            a10 = ffma2(p1.u.p01, eR[t][0][0], a10);                             \
            a11 = ffma2(p1.u.p01, eR[t][0][1], a11);                             \
            a00 = ffma2(p0.u.p23, eR[t][1][0], a00);                             \
            a01 = ffma2(p0.u.p23, eR[t][1][1], a01);                             \
            a10 = ffma2(p1.u.p23, eR[t][1][0], a10);                             \
            a11 = ffma2(p1.u.p23, eR[t][1][1], a11);                             \
        }                                                                        \
        float2 h;                                                                \
        h = unpackf2(a00); float f00 = h.x + h.y;   /* b0,k0 */                  \
        h = unpackf2(a01); float f01 = h.x + h.y;   /* b0,k1 */                  \
        h = unpackf2(a10); float f10 = h.x + h.y;   /* b1,k0 */                  \
        h = unpackf2(a11); float f11 = h.x + h.y;   /* b1,k1 */                  \
        /* level ^8 (partner differs in ab): send partner's batch, keep own */   \
        float sendA = ab ? f00 : f10;                                            \
        float sendB = ab ? f01 : f11;                                            \
        float g0 = (ab ? f10 : f00) + __shfl_xor_sync(0xffffffffu, sendA, 8);    \
        float g1 = (ab ? f11 : f01) + __shfl_xor_sync(0xffffffffu, sendB, 8);    \
        /* level ^16 (partner differs in ak): send partner's k, keep own */      \
        float sendC = ak ? g0 : g1;                                              \
        float mine  = (ak ? g1 : g0) + __shfl_xor_sync(0xffffffffu, sendC, 16);  \
        if (m) { myp = mine * factor; e_acc += es; }                             \
        (Pout)[ka] = myp;                                                        \
        em = nem; m = nm;                                                        \
        __syncthreads();                                                         \
    }

    // 511 steps: 255 unrolled pairs (steps 1..510, prefetching) + final step 511
    for (int i = 0; i < 255; ++i) {
        STEP(sPA, sPB, 1);
        STEP(sPB, sPA, 1);
    }
    STEP(sPA, sPB, 0);
    #undef STEP

    // ---- finalize: logZ = e_acc*ln2 + log( sum_k p~[k]*exp(end[k]) ) ----
    sZf[ab][myk] = myp * __expf(end_t[myk]);
    if (w == 0 && kidx == 0 && ak == 0) sEa[ab] = e_acc;  // lanes 0 (ab=0), 8 (ab=1)
    __syncthreads();
    if (w == 0) {
        #pragma unroll
        for (int b = 0; b < NBC; ++b) {
            float v = sZf[b][lane] + sZf[b][lane + 32]
                    + sZf[b][lane + 64] + sZf[b][lane + 96];
            v += __shfl_xor_sync(0xffffffffu, v, 1);
            v += __shfl_xor_sync(0xffffffffu, v, 2);
            v += __shfl_xor_sync(0xffffffffu, v, 4);
            v += __shfl_xor_sync(0xffffffffu, v, 8);
            v += __shfl_xor_sync(0xffffffffu, v, 16);
            if (lane == 0)
                g_logZ[blockIdx.x * NBC + b] = (float)sEa[b] * LN2F + logf(v);
        }
    }
}

// Numerator: one block per batch.
__global__ void crf_num(const float* __restrict__ emissions,
                        const int*   __restrict__ tags,
                        const int*   __restrict__ mask,
                        const float* __restrict__ start_t,
                        const float* __restrict__ end_t,
                        const float* __restrict__ trans)
{
    const int b   = blockIdx.x;
    const int tid = threadIdx.x;
    __shared__ float rf[256];
    __shared__ int   ri[256];

    float loc = 0.f;
    int   cnt = 0;
    for (int i = tid; i < LL; i += 256) {
        int tag = tags[i * BB + b];
        int m   = mask[i * BB + b];
        if (m) {
            loc += emissions[((size_t)i * BB + b) * TT + tag];
            cnt++;
            if (i > 0) loc += trans[tags[(i - 1) * BB + b] * TT + tag];
        }
        if (i == 0) loc += start_t[tag];
    }
    rf[tid] = loc; ri[tid] = cnt;
    __syncthreads();
    #pragma unroll
    for (int s = 128; s > 0; s >>= 1) {
        if (tid < s) { rf[tid] += rf[tid + s]; ri[tid] += ri[tid + s]; }
        __syncthreads();
    }
    if (tid == 0) {
        int ends = ri[0] - 1;
        if (ends < 0) ends = 0;
        g_num[b] = rf[0] + end_t[tags[ends * BB + b]];
    }
}

__global__ void crf_final(float* __restrict__ out)
{
    __shared__ float r[512];
    const int tid = threadIdx.x;
    r[tid] = g_logZ[tid] - g_num[tid];
    __syncthreads();
    #pragma unroll
    for (int s = 256; s > 0; s >>= 1) {
        if (tid < s) r[tid] += r[tid + s];
        __syncthreads();
    }
    if (tid == 0) out[0] = r[0] * (1.0f / (float)BB);
}

extern "C" void kernel_launch(void* const* d_in, const int* in_sizes, int n_in,
                              void* d_out, int out_size)
{
    const float* emissions = (const float*)d_in[0];
    const int*   tags      = (const int*)d_in[1];
    const int*   mask      = (const int*)d_in[2];
    const float* start_t   = (const float*)d_in[3];
    const float* end_t     = (const float*)d_in[4];
    const float* trans     = (const float*)d_in[5];
    float*       out       = (float*)d_out;

    crf_forward<<<NCTA, NTHREADS>>>(emissions, mask, start_t, end_t, trans);
    crf_num<<<BB, 256>>>(emissions, tags, mask, start_t, end_t, trans);
    crf_final<<<1, BB>>>(out);
}

// round 14
// speedup vs baseline: 1.1697x; 1.0683x over previous
#include <cuda_runtime.h>
#include <math.h>
#include <stdint.h>

// CRF loss: L=512 seq, B=512 batch, T=128 tags.
#define LL 512
#define BB 512
#define TT 128
#define NBC 2             // batches per CTA
#define NCTA (BB/NBC)     // 256 CTAs -> 2 CTAs/SM
#define NTHREADS 256
#define PQ 36             // padded j-quarter stride (floats)
#define PB (4*PQ)         // padded per-batch alpha row = 144 floats
#define LN2F 0.6931471805599453f

__device__ float g_logZ[BB];
__device__ float g_num[BB];

union F4U { float4 v; struct { unsigned long long p01, p23; } u; };

__device__ __forceinline__ unsigned long long ffma2(unsigned long long a,
                                                    unsigned long long b,
                                                    unsigned long long c) {
    unsigned long long d;
    asm("fma.rn.f32x2 %0, %1, %2, %3;" : "=l"(d) : "l"(a), "l"(b), "l"(c));
    return d;
}
__device__ __forceinline__ unsigned long long packf2(float lo, float hi) {
    unsigned long long r;
    asm("mov.b64 %0, {%1,%2};" : "=l"(r) : "f"(lo), "f"(hi));
    return r;
}
__device__ __forceinline__ float2 unpackf2(unsigned long long v) {
    float2 f;
    asm("mov.b64 {%0,%1}, %2;" : "=f"(f.x), "=f"(f.y) : "l"(v));
    return f;
}

// Org (R8 champion shape): 8 warps, 2 batches/CTA, 2 CTAs/SM. Lane: jq=lane>>3
// (j-quarter), kidx=lane&7, k0=w*16+kidx*2. Tile: 32j x 2k x 2b = 64 FFMA2/step.
// E: 32 u64 regs. Tail: R8's 8-shfl tree. NEW: 2-step-deep __ldcs prefetch of
// emissions/mask via pointer increments; pass-through value in register (myp).
__global__ __launch_bounds__(NTHREADS, 2)
void crf_forward(const float* __restrict__ emissions,
                 const int* __restrict__ mask,
                 const float* __restrict__ start_t,
                 const float* __restrict__ end_t,
                 const float* __restrict__ trans)
{
    __shared__ __align__(16) float sPA[NBC * PB];   // ping
    __shared__ __align__(16) float sPB[NBC * PB];   // pong
    __shared__ __align__(16) float sZf[NBC][TT];
    __shared__ int sEa[NBC];

    const int tid  = threadIdx.x;
    const int w    = tid >> 5;
    const int lane = tid & 31;
    const int jq   = lane >> 3;
    const int kidx = lane & 7;
    const int k0   = w * 16 + kidx * 2;
    const int ab   = jq & 1;             // assigned local batch
    const int ak   = jq >> 1;            // assigned k within pair
    const int myk  = k0 + ak;
    const int gba  = blockIdx.x * NBC + ab;
    const int ka   = ab * PB + (myk >> 5) * PQ + (myk & 31);  // addr of my element
    const int jb   = jq * PQ;            // lane's j-quarter offset within a row
    const int ebase = ab * PB;           // my batch row base (scale est)

    // ---- E: 32 j x 2 k per lane, register-resident ----
    unsigned long long eR[8][2][2];
    #pragma unroll
    for (int t = 0; t < 8; ++t) {
        #pragma unroll
        for (int sub = 0; sub < 2; ++sub) {
            int j = jq * 32 + t * 4 + sub * 2;
            eR[t][sub][0] = packf2(__expf(trans[j * TT + k0]),
                                   __expf(trans[(j + 1) * TT + k0]));
            eR[t][sub][1] = packf2(__expf(trans[j * TT + k0 + 1]),
                                   __expf(trans[(j + 1) * TT + k0 + 1]));
        }
    }

    // ---- init: p~0[ab][myk], kept in register ----
    float myp = __expf(start_t[myk] + emissions[(size_t)gba * TT + myk]);
    sPA[ka] = myp;
    __syncthreads();

    int e_acc = 0;

    // 2-deep emission/mask prefetch pipeline (pointer-increment only)
    const size_t ESTRIDE = (size_t)BB * TT;
    const float* ep = emissions + ((size_t)2 * BB + gba) * TT + myk;  // -> step 2
    const int*   mp = mask + 2 * BB + gba;
    float em_c = __ldcs(emissions + ((size_t)1 * BB + gba) * TT + myk);  // step 1
    int   m_c  = mask[1 * BB + gba];
    float em_n = __ldcs(ep);                                             // step 2
    int   m_n  = *mp;

    // ---- one step: Pin -> Pout; PF=1 while steps remain to prefetch ----
    #define STEP(Pin, Pout, PF)                                                 \
    {                                                                            \
        const float4 ev = *(const float4*)&(Pin)[ebase];                         \
        float s  = (ev.x + ev.y) + (ev.z + ev.w);                                \
        int   es = ((__float_as_int(s) >> 23) & 255) - 126;                      \
        float factor = __expf(em_c) * __int_as_float((127 - es) << 23);          \
        float em_f = 0.f; int m_f = 0;                                           \
        if (PF) { ep += ESTRIDE; mp += BB; em_f = __ldcs(ep); m_f = *mp; }       \
        unsigned long long a00 = 0, a01 = 0, a10 = 0, a11 = 0;                   \
        _Pragma("unroll")                                                        \
        for (int t = 0; t < 8; ++t) {                                            \
            F4U p0; p0.v = *(const float4*)((Pin) + jb + 4 * t);                 \
            F4U p1; p1.v = *(const float4*)((Pin) + PB + jb + 4 * t);            \
            a00 = ffma2(p0.u.p01, eR[t][0][0], a00);                             \
            a01 = ffma2(p0.u.p01, eR[t][0][1], a01);                             \
            a10 = ffma2(p1.u.p01, eR[t][0][0], a10);                             \
            a11 = ffma2(p1.u.p01, eR[t][0][1], a11);                             \
            a00 = ffma2(p0.u.p23, eR[t][1][0], a00);                             \
            a01 = ffma2(p0.u.p23, eR[t][1][1], a01);                             \
            a10 = ffma2(p1.u.p23, eR[t][1][0], a10);                             \
            a11 = ffma2(p1.u.p23, eR[t][1][1], a11);                             \
        }                                                                        \
        float2 h;                                                                \
        h = unpackf2(a00); float f00 = h.x + h.y;                                \
        h = unpackf2(a01); float f01 = h.x + h.y;                                \
        h = unpackf2(a10); float f10 = h.x + h.y;                                \
        h = unpackf2(a11); float f11 = h.x + h.y;                                \
        f00 += __shfl_xor_sync(0xffffffffu, f00, 8);                             \
        f01 += __shfl_xor_sync(0xffffffffu, f01, 8);                             \
        f10 += __shfl_xor_sync(0xffffffffu, f10, 8);                             \
        f11 += __shfl_xor_sync(0xffffffffu, f11, 8);                             \
        f00 += __shfl_xor_sync(0xffffffffu, f00, 16);                            \
        f01 += __shfl_xor_sync(0xffffffffu, f01, 16);                            \
        f10 += __shfl_xor_sync(0xffffffffu, f10, 16);                            \
        f11 += __shfl_xor_sync(0xffffffffu, f11, 16);                            \
        float mine = ab ? (ak ? f11 : f10) : (ak ? f01 : f00);                   \
        if (m_c) { myp = mine * factor; e_acc += es; }                           \
        (Pout)[ka] = myp;                                                        \
        em_c = em_n; m_c = m_n;                                                  \
        em_n = em_f; m_n = m_f;                                                  \
        __syncthreads();                                                         \
    }

    // 511 steps. Prefetch runs through step 509 (loads for step 511);
    // the last two steps consume the pipeline without loading.
    for (int i = 0; i < 254; ++i) {
        STEP(sPA, sPB, 1);
        STEP(sPB, sPA, 1);
    }
    STEP(sPA, sPB, 1);   // step 509
    STEP(sPB, sPA, 0);   // step 510
    STEP(sPA, sPB, 0);   // step 511
    #undef STEP

    // ---- finalize: logZ = e_acc*ln2 + log( sum_k p~[k]*exp(end[k]) ) ----
    sZf[ab][myk] = myp * __expf(end_t[myk]);
    if (w == 0 && kidx == 0 && ak == 0) sEa[ab] = e_acc;   // lanes 0 (ab=0), 8 (ab=1)
    __syncthreads();
    if (w == 0) {
        #pragma unroll
        for (int b = 0; b < NBC; ++b) {
            float v = sZf[b][lane] + sZf[b][lane + 32]
                    + sZf[b][lane + 64] + sZf[b][lane + 96];
            v += __shfl_xor_sync(0xffffffffu, v, 1);
            v += __shfl_xor_sync(0xffffffffu, v, 2);
            v += __shfl_xor_sync(0xffffffffu, v, 4);
            v += __shfl_xor_sync(0xffffffffu, v, 8);
            v += __shfl_xor_sync(0xffffffffu, v, 16);
            if (lane == 0)
                g_logZ[blockIdx.x * NBC + b] = (float)sEa[b] * LN2F + logf(v);
        }
    }
}

// Numerator: one block per batch.
__global__ void crf_num(const float* __restrict__ emissions,
                        const int*   __restrict__ tags,
                        const int*   __restrict__ mask,
                        const float* __restrict__ start_t,
                        const float* __restrict__ end_t,
                        const float* __restrict__ trans)
{
    const int b   = blockIdx.x;
    const int tid = threadIdx.x;
    __shared__ float rf[256];
    __shared__ int   ri[256];

    float loc = 0.f;
    int   cnt = 0;
    for (int i = tid; i < LL; i += 256) {
        int tag = tags[i * BB + b];
        int m   = mask[i * BB + b];
        if (m) {
            loc += emissions[((size_t)i * BB + b) * TT + tag];
            cnt++;
            if (i > 0) loc += trans[tags[(i - 1) * BB + b] * TT + tag];
        }
        if (i == 0) loc += start_t[tag];
    }
    rf[tid] = loc; ri[tid] = cnt;
    __syncthreads();
    #pragma unroll
    for (int s = 128; s > 0; s >>= 1) {
        if (tid < s) { rf[tid] += rf[tid + s]; ri[tid] += ri[tid + s]; }
        __syncthreads();
    }
    if (tid == 0) {
        int ends = ri[0] - 1;
        if (ends < 0) ends = 0;
        g_num[b] = rf[0] + end_t[tags[ends * BB + b]];
    }
}

__global__ void crf_final(float* __restrict__ out)
{
    __shared__ float r[512];
    const int tid = threadIdx.x;
    r[tid] = g_logZ[tid] - g_num[tid];
    __syncthreads();
    #pragma unroll
    for (int s = 256; s > 0; s >>= 1) {
        if (tid < s) r[tid] += r[tid + s];
        __syncthreads();
    }
    if (tid == 0) out[0] = r[0] * (1.0f / (float)BB);
}

extern "C" void kernel_launch(void* const* d_in, const int* in_sizes, int n_in,
                              void* d_out, int out_size)
{
    const float* emissions = (const float*)d_in[0];
    const int*   tags      = (const int*)d_in[1];
    const int*   mask      = (const int*)d_in[2];
    const float* start_t   = (const float*)d_in[3];
    const float* end_t     = (const float*)d_in[4];
    const float* trans     = (const float*)d_in[5];
    float*       out       = (float*)d_out;

    crf_forward<<<NCTA, NTHREADS>>>(emissions, mask, start_t, end_t, trans);
    crf_num<<<BB, 256>>>(emissions, tags, mask, start_t, end_t, trans);
    crf_final<<<1, BB>>>(out);
}

// round 15
// speedup vs baseline: 1.2680x; 1.0841x over previous
#include <cuda_runtime.h>
#include <math.h>
#include <stdint.h>

// CRF loss: L=512 seq, B=512 batch, T=128 tags.
#define LL 512
#define BB 512
#define TT 128
#define NBC 2             // batches per CTA
#define NCTA (BB/NBC)     // 256 CTAs -> 2 CTAs/SM
#define NTHREADS 256
#define PQ 36             // padded j-quarter stride (floats)
#define PB (4*PQ)         // padded per-batch alpha row = 144 floats
#define LN2F 0.6931471805599453f

__device__ float g_logZ[BB];
__device__ float g_num[BB];

union F4U { float4 v; struct { unsigned long long p01, p23; } u; };

__device__ __forceinline__ unsigned long long ffma2(unsigned long long a,
                                                    unsigned long long b,
                                                    unsigned long long c) {
    unsigned long long d;
    asm("fma.rn.f32x2 %0, %1, %2, %3;" : "=l"(d) : "l"(a), "l"(b), "l"(c));
    return d;
}
__device__ __forceinline__ unsigned long long packf2(float lo, float hi) {
    unsigned long long r;
    asm("mov.b64 %0, {%1,%2};" : "=l"(r) : "f"(lo), "f"(hi));
    return r;
}
__device__ __forceinline__ float2 unpackf2(unsigned long long v) {
    float2 f;
    asm("mov.b64 {%0,%1}, %2;" : "=f"(f.x), "=f"(f.y) : "l"(v));
    return f;
}

// Org (R8/R14 champion shape): 8 warps, 2 batches/CTA, 2 CTAs/SM. Lane:
// jq=lane>>3 (j-quarter), kidx=lane&7, k0=w*16+kidx*2. Tile: 32j x 2k x 2b =
// 64 FFMA2/step. E: 32 u64 regs. Tail: 8-shfl tree. NEW in R15:
//  - scale from single word p'[b][0] via 2-op bit math (LDS.32 -> AND -> ISUB)
//  - exp(emission) pipelined one step ahead (MUFU off the critical chain)
__global__ __launch_bounds__(NTHREADS, 2)
void crf_forward(const float* __restrict__ emissions,
                 const int* __restrict__ mask,
                 const float* __restrict__ start_t,
                 const float* __restrict__ end_t,
                 const float* __restrict__ trans)
{
    __shared__ __align__(16) float sPA[NBC * PB];   // ping
    __shared__ __align__(16) float sPB[NBC * PB];   // pong
    __shared__ __align__(16) float sZf[NBC][TT];
    __shared__ int sEa[NBC];

    const int tid  = threadIdx.x;
    const int w    = tid >> 5;
    const int lane = tid & 31;
    const int jq   = lane >> 3;
    const int kidx = lane & 7;
    const int k0   = w * 16 + kidx * 2;
    const int ab   = jq & 1;             // assigned local batch
    const int ak   = jq >> 1;            // assigned k within pair
    const int myk  = k0 + ak;
    const int gba  = blockIdx.x * NBC + ab;
    const int ka   = ab * PB + (myk >> 5) * PQ + (myk & 31);  // addr of my element
    const int jb   = jq * PQ;            // lane's j-quarter offset within a row
    const int ebase = ab * PB;           // my batch row base (scale est = p'[b][0])

    // ---- E: 32 j x 2 k per lane, register-resident ----
    unsigned long long eR[8][2][2];
    #pragma unroll
    for (int t = 0; t < 8; ++t) {
        #pragma unroll
        for (int sub = 0; sub < 2; ++sub) {
            int j = jq * 32 + t * 4 + sub * 2;
            eR[t][sub][0] = packf2(__expf(trans[j * TT + k0]),
                                   __expf(trans[(j + 1) * TT + k0]));
            eR[t][sub][1] = packf2(__expf(trans[j * TT + k0 + 1]),
                                   __expf(trans[(j + 1) * TT + k0 + 1]));
        }
    }

    // ---- init: p~0[ab][myk], kept in register ----
    float myp = __expf(start_t[myk] + emissions[(size_t)gba * TT + myk]);
    sPA[ka] = myp;
    __syncthreads();

    int e_acc = 0;

    // 2-deep emission/mask prefetch pipeline (pointer-increment only)
    const size_t ESTRIDE = (size_t)BB * TT;
    const float* ep = emissions + ((size_t)2 * BB + gba) * TT + myk;  // -> step 2
    const int*   mp = mask + 2 * BB + gba;
    float em_c = __ldcs(emissions + ((size_t)1 * BB + gba) * TT + myk);  // step 1
    int   m_c  = mask[1 * BB + gba];
    float em_n = __ldcs(ep);                                             // step 2
    int   m_n  = *mp;
    float xq_c = __expf(em_c);            // exp(emission) for the CURRENT step

    // ---- one step: Pin -> Pout; PF=1 while steps remain to prefetch ----
    #define STEP(Pin, Pout, PF)                                                 \
    {                                                                            \
        unsigned int pe = *(const unsigned int*)&(Pin)[ebase];  /* p'[b][0] */   \
        float scale = __int_as_float(0x7E800000 - (int)(pe & 0x7F800000u));      \
        float factor = xq_c * scale;                                             \
        int   es = (int)((pe >> 23) & 255u) - 126;                               \
        float xq_n = __expf(em_n);        /* next step's exp, off-chain */       \
        float em_f = 0.f; int m_f = 0;                                           \
        if (PF) { ep += ESTRIDE; mp += BB; em_f = __ldcs(ep); m_f = *mp; }       \
        unsigned long long a00 = 0, a01 = 0, a10 = 0, a11 = 0;                   \
        _Pragma("unroll")                                                        \
        for (int t = 0; t < 8; ++t) {                                            \
            F4U p0; p0.v = *(const float4*)((Pin) + jb + 4 * t);                 \
            F4U p1; p1.v = *(const float4*)((Pin) + PB + jb + 4 * t);            \
            a00 = ffma2(p0.u.p01, eR[t][0][0], a00);                             \
            a01 = ffma2(p0.u.p01, eR[t][0][1], a01);                             \
            a10 = ffma2(p1.u.p01, eR[t][0][0], a10);                             \
            a11 = ffma2(p1.u.p01, eR[t][0][1], a11);                             \
            a00 = ffma2(p0.u.p23, eR[t][1][0], a00);                             \
            a01 = ffma2(p0.u.p23, eR[t][1][1], a01);                             \
            a10 = ffma2(p1.u.p23, eR[t][1][0], a10);                             \
            a11 = ffma2(p1.u.p23, eR[t][1][1], a11);                             \
        }                                                                        \
        float2 h;                                                                \
        h = unpackf2(a00); float f00 = h.x + h.y;                                \
        h = unpackf2(a01); float f01 = h.x + h.y;                                \
        h = unpackf2(a10); float f10 = h.x + h.y;                                \
        h = unpackf2(a11); float f11 = h.x + h.y;                                \
        f00 += __shfl_xor_sync(0xffffffffu, f00, 8);                             \
        f01 += __shfl_xor_sync(0xffffffffu, f01, 8);                             \
        f10 += __shfl_xor_sync(0xffffffffu, f10, 8);                             \
        f11 += __shfl_xor_sync(0xffffffffu, f11, 8);                             \
        f00 += __shfl_xor_sync(0xffffffffu, f00, 16);                            \
        f01 += __shfl_xor_sync(0xffffffffu, f01, 16);                            \
        f10 += __shfl_xor_sync(0xffffffffu, f10, 16);                            \
        f11 += __shfl_xor_sync(0xffffffffu, f11, 16);                            \
        float mine = ab ? (ak ? f11 : f10) : (ak ? f01 : f00);                   \
        if (m_c) { myp = mine * factor; e_acc += es; }                           \
        (Pout)[ka] = myp;                                                        \
        em_c = em_n; m_c = m_n;                                                  \
        em_n = em_f; m_n = m_f;                                                  \
        xq_c = xq_n;                                                             \
        __syncthreads();                                                         \
    }

    // 511 steps. Prefetch runs through step 509 (loads for step 511);
    // the last two steps consume the pipeline without loading.
    for (int i = 0; i < 254; ++i) {
        STEP(sPA, sPB, 1);
        STEP(sPB, sPA, 1);
    }
    STEP(sPA, sPB, 1);   // step 509
    STEP(sPB, sPA, 0);   // step 510
    STEP(sPA, sPB, 0);   // step 511
    #undef STEP

    // ---- finalize: logZ = e_acc*ln2 + log( sum_k p~[k]*exp(end[k]) ) ----
    sZf[ab][myk] = myp * __expf(end_t[myk]);
    if (w == 0 && kidx == 0 && ak == 0) sEa[ab] = e_acc;   // lanes 0 (ab=0), 8 (ab=1)
    __syncthreads();
    if (w == 0) {
        #pragma unroll
        for (int b = 0; b < NBC; ++b) {
            float v = sZf[b][lane] + sZf[b][lane + 32]
                    + sZf[b][lane + 64] + sZf[b][lane + 96];
            v += __shfl_xor_sync(0xffffffffu, v, 1);
            v += __shfl_xor_sync(0xffffffffu, v, 2);
            v += __shfl_xor_sync(0xffffffffu, v, 4);
            v += __shfl_xor_sync(0xffffffffu, v, 8);
            v += __shfl_xor_sync(0xffffffffu, v, 16);
            if (lane == 0)
                g_logZ[blockIdx.x * NBC + b] = (float)sEa[b] * LN2F + logf(v);
        }
    }
}

// Numerator: one block per batch.
__global__ void crf_num(const float* __restrict__ emissions,
                        const int*   __restrict__ tags,
                        const int*   __restrict__ mask,
                        const float* __restrict__ start_t,
                        const float* __restrict__ end_t,
                        const float* __restrict__ trans)
{
    const int b   = blockIdx.x;
    const int tid = threadIdx.x;
    __shared__ float rf[256];
    __shared__ int   ri[256];

    float loc = 0.f;
    int   cnt = 0;
    for (int i = tid; i < LL; i += 256) {
        int tag = tags[i * BB + b];
        int m   = mask[i * BB + b];
        if (m) {
            loc += emissions[((size_t)i * BB + b) * TT + tag];
            cnt++;
            if (i > 0) loc += trans[tags[(i - 1) * BB + b] * TT + tag];
        }
        if (i == 0) loc += start_t[tag];
    }
    rf[tid] = loc; ri[tid] = cnt;
    __syncthreads();
    #pragma unroll
    for (int s = 128; s > 0; s >>= 1) {
        if (tid < s) { rf[tid] += rf[tid + s]; ri[tid] += ri[tid + s]; }
        __syncthreads();
    }
    if (tid == 0) {
        int ends = ri[0] - 1;
        if (ends < 0) ends = 0;
        g_num[b] = rf[0] + end_t[tags[ends * BB + b]];
    }
}

__global__ void crf_final(float* __restrict__ out)
{
    __shared__ float r[512];
    const int tid = threadIdx.x;
    r[tid] = g_logZ[tid] - g_num[tid];
    __syncthreads();
    #pragma unroll
    for (int s = 256; s > 0; s >>= 1) {
        if (tid < s) r[tid] += r[tid + s];
        __syncthreads();
    }
    if (tid == 0) out[0] = r[0] * (1.0f / (float)BB);
}

extern "C" void kernel_launch(void* const* d_in, const int* in_sizes, int n_in,
                              void* d_out, int out_size)
{
    const float* emissions = (const float*)d_in[0];
    const int*   tags      = (const int*)d_in[1];
    const int*   mask      = (const int*)d_in[2];
    const float* start_t   = (const float*)d_in[3];
    const float* end_t     = (const float*)d_in[4];
    const float* trans     = (const float*)d_in[5];
    float*       out       = (float*)d_out;

    crf_forward<<<NCTA, NTHREADS>>>(emissions, mask, start_t, end_t, trans);
    crf_num<<<BB, 256>>>(emissions, tags, mask, start_t, end_t, trans);
    crf_final<<<1, BB>>>(out);
}